// round 15
// baseline (speedup 1.0000x reference)
#include <cuda_runtime.h>
#include <cstdint>

#define HH 19
#define CELLS 361
#define MASK19 0x7FFFFu
#define NT 512
#define WPB 16                // warps per block
#define FULLM 0xFFFFFFFFu

#define ONEF   0x3F800000u   // 1.0f
#define ONEF_2 0x1FC00000u   // *2 -> 1.0f
#define ONEF_4 0x0FE00000u   // *4 -> 1.0f
#define ONEF_8 0x07F00000u   // *8 -> 1.0f
#define TWOF   0x40000000u   // 2.0f
#define TWOF_2 0x20000000u
#define TWOF_4 0x10000000u
#define TWOF_8 0x08000000u
#define FOURF   0x40800000u  // 4.0f
#define FOURF_2 0x20400000u
#define FOURF_4 0x10200000u
#define FOURF_8 0x08100000u

// weak = opp stone with exactly one orthogonal opp neighbor
__device__ __forceinline__ uint32_t weak_row(uint32_t om, uint32_t ou, uint32_t od) {
    const uint32_t ol  = (om << 1) & MASK19;
    const uint32_t orr = om >> 1;
    const uint32_t par = ou ^ od ^ ol ^ orr;
    const uint32_t ge2 = (ou & od) | (ol & orr) | ((ou | od) & (ol | orr));
    return om & par & ~ge2;
}

// expand a 361-bit stream (word w in lane w, w=0..11) of 0/1 bits to floats
__device__ __forceinline__ void expand_binary(float* __restrict__ out,
                                              size_t gb, uint32_t S, int lane) {
    float* o = out + gb;
    const int s  = (int)((4u - ((uint32_t)gb & 3u)) & 3u);
    const int ng = (CELLS - s) >> 2;
    const int tb = s + 4 * ng;
    const int tc = CELLS - tb;
    float4* o4 = (float4*)(o + s);
    const uint32_t h = __shfl_sync(FULLM, S, 0);
    const uint32_t e = __shfl_sync(FULLM, S, 11);
    if (lane < s)  __stcs(o + lane, __uint_as_float(((h >> lane) & 1u) * ONEF));
    if (lane < tc) __stcs(o + tb + lane,
                          __uint_as_float(((e >> (tb + lane - 352)) & 1u) * ONEF));
#pragma unroll
    for (int it = 0; it < 3; ++it) {
        const int j  = it * 32 + lane;
        const int bp = s + 4 * j;
        const int q  = bp >> 5, sh = bp & 31;
        const uint32_t pr = __funnelshift_r(__shfl_sync(FULLM, S, q),
                                            __shfl_sync(FULLM, S, (q + 1) & 31), sh);
        float4 v;
        v.x = __uint_as_float((pr & 1u) * ONEF);
        v.y = __uint_as_float((pr & 2u) * ONEF_2);
        v.z = __uint_as_float((pr & 4u) * ONEF_4);
        v.w = __uint_as_float((pr & 8u) * ONEF_8);
        if (j < ng) __stcs(o4 + j, v);
    }
}

__global__ __launch_bounds__(NT, 3)
void go_feat_kernel(const float* __restrict__ stones,
                    const int*   __restrict__ cur_player,
                    const int*   __restrict__ ko_points,
                    float*       __restrict__ out,
                    int B)
{
    const int lane    = threadIdx.x & 31;
    const int nwtotal = gridDim.x * WPB;
    const int w0      = blockIdx.x * WPB + (threadIdx.x >> 5);

    // persistent grid-stride loop over boards (warp-uniform)
    for (int b = w0; b < B; b += nwtotal) {
        const int cp = cur_player[b];         // broadcast loads
        const int kr = ko_points[2 * b];
        const int kc = ko_points[2 * b + 1];

        // ---- 1: ballot-pack the board's 722 floats; word k parked in lane k ----
        const float* src = stones + (size_t)b * 722;
        uint32_t W = 0u;
#pragma unroll
        for (int k = 0; k < 23; ++k) {
            const int e = (k << 5) + lane;
            float v = 0.0f;
            if (e < 722) v = __ldcs(src + e);
            const unsigned bal = __ballot_sync(FULLM, v > 0.5f);
            if (lane == k) W = bal;
        }

        // ---- 2: row masks; lane r = row r (lanes >= 19 forced to 0) ----
        const int bit0 = HH * lane;
        const uint32_t m0 = __funnelshift_r(__shfl_sync(FULLM, W, (bit0 >> 5) & 31),
                                            __shfl_sync(FULLM, W, ((bit0 >> 5) + 1) & 31),
                                            bit0) & MASK19;
        const int bit1 = bit0 + CELLS;
        const uint32_t m1 = __funnelshift_r(__shfl_sync(FULLM, W, (bit1 >> 5) & 31),
                                            __shfl_sync(FULLM, W, ((bit1 >> 5) + 1) & 31),
                                            bit1) & MASK19;
        const bool rowok = lane < HH;
        const uint32_t curb = rowok ? (cp ? m1 : m0) : 0u;
        const uint32_t oppb = rowok ? (cp ? m0 : m1) : 0u;
        const uint32_t empb = rowok ? ((~(m0 | m1)) & MASK19) : 0u;

        // ---- 3: stencils, lane-parallel (wrap-around shfl hits zeroed lanes) ----
        const uint32_t ou = __shfl_sync(FULLM, oppb, (lane - 1) & 31);
        const uint32_t od = __shfl_sync(FULLM, oppb, (lane + 1) & 31);
        const uint32_t wk  = weak_row(oppb, ou, od);
        const uint32_t wku = __shfl_sync(FULLM, wk, (lane - 1) & 31);
        const uint32_t wkd = __shfl_sync(FULLM, wk, (lane + 1) & 31);
        const uint32_t eu = __shfl_sync(FULLM, empb, (lane - 1) & 31);
        const uint32_t ed = __shfl_sync(FULLM, empb, (lane + 1) & 31);

        uint32_t legal = empb & (eu | ed | ((empb << 1) & MASK19) | (empb >> 1)
                       | wku | wkd | ((wk << 1) & MASK19) | (wk >> 1));
        if (kr >= 0) {
            const int rr = kr > (HH - 1) ? (HH - 1) : kr;
            int cc = kc < 0 ? 0 : (kc > (HH - 1) ? (HH - 1) : kc);
            if (lane == rr) legal &= ~(1u << cc);
        }

        const uint32_t cu = __shfl_sync(FULLM, curb, (lane - 1) & 31);
        const uint32_t cd = __shfl_sync(FULLM, curb, (lane + 1) & 31);
        const uint32_t cl = (curb << 1) & MASK19;
        const uint32_t cr = curb >> 1;
        const uint32_t sab = cu ^ cd,  cab = cu & cd;
        const uint32_t scd = cl ^ cr,  ccd = cl & cr;
        const uint32_t kx  = sab & scd;
        const uint32_t p0 = (sab ^ scd)      & empb;   // ones
        const uint32_t p1 = (cab ^ ccd ^ kx) & empb;   // twos
        const uint32_t p2 = (cab & ccd)      & empb;   // fours

        // ---- 4: build 361-bit streams (word w in lane w, w = 0..11) ----
        const int w32 = lane << 5;
        const int r0  = w32 / HH;
        uint32_t ls = 0u, a0 = 0u, a1 = 0u, a2 = 0u;
#pragma unroll
        for (int i = 0; i < 3; ++i) {
            const int r  = r0 + i;
            const int sh = HH * r - w32;               // (-19, 39)
            const uint32_t lm = __shfl_sync(FULLM, legal, r & 31);
            const uint32_t q0 = __shfl_sync(FULLM, p0,    r & 31);
            const uint32_t q1 = __shfl_sync(FULLM, p1,    r & 31);
            const uint32_t q2 = __shfl_sync(FULLM, p2,    r & 31);
            if (sh >= 0) {
                if (sh < 32) {
                    ls |= lm << sh; a0 |= q0 << sh; a1 |= q1 << sh; a2 |= q2 << sh;
                }
            } else {
                ls |= lm >> (-sh); a0 |= q0 >> (-sh); a1 |= q1 >> (-sh); a2 |= q2 >> (-sh);
            }
        }
        // cur/opp streams come free from the packed input bits
        const int pbase = cp * CELLS + w32;
        const uint32_t cur_s = __funnelshift_r(__shfl_sync(FULLM, W, (pbase >> 5) & 31),
                                               __shfl_sync(FULLM, W, ((pbase >> 5) + 1) & 31),
                                               pbase);
        const int obase = (1 - cp) * CELLS + w32;
        const uint32_t opp_s = __funnelshift_r(__shfl_sync(FULLM, W, (obase >> 5) & 31),
                                               __shfl_sync(FULLM, W, ((obase >> 5) + 1) & 31),
                                               obase);

        // ---- 5: expansion, 5 channels ----
        const size_t gb0 = (size_t)b * 1805;
        expand_binary(out, gb0,             cur_s, lane);
        expand_binary(out, gb0 + CELLS,     opp_s, lane);
        expand_binary(out, gb0 + 2 * CELLS, ls,    lane);

        {   // ch3: liberties (0..7, exact)
            const size_t gb = gb0 + 3 * CELLS;
            float* o = out + gb;
            const int s  = (int)((4u - ((uint32_t)gb & 3u)) & 3u);
            const int ng = (CELLS - s) >> 2;
            const int tb = s + 4 * ng;
            const int tc = CELLS - tb;
            float4* o4 = (float4*)(o + s);
            const uint32_t h0 = __shfl_sync(FULLM, a0, 0);
            const uint32_t h1 = __shfl_sync(FULLM, a1, 0);
            const uint32_t h2 = __shfl_sync(FULLM, a2, 0);
            const uint32_t e0 = __shfl_sync(FULLM, a0, 11);
            const uint32_t e1 = __shfl_sync(FULLM, a1, 11);
            const uint32_t e2 = __shfl_sync(FULLM, a2, 11);
            if (lane < s) {
                __stcs(o + lane,
                       __uint_as_float(((h0 >> lane) & 1u) * ONEF)
                     + __uint_as_float(((h1 >> lane) & 1u) * TWOF)
                     + __uint_as_float(((h2 >> lane) & 1u) * FOURF));
            }
            if (lane < tc) {
                const int sh = tb + lane - 352;
                __stcs(o + tb + lane,
                       __uint_as_float(((e0 >> sh) & 1u) * ONEF)
                     + __uint_as_float(((e1 >> sh) & 1u) * TWOF)
                     + __uint_as_float(((e2 >> sh) & 1u) * FOURF));
            }
#pragma unroll
            for (int it = 0; it < 3; ++it) {
                const int j  = it * 32 + lane;
                const int bp = s + 4 * j;
                const int q  = bp >> 5, sh = bp & 31;
                const uint32_t r0w = __funnelshift_r(__shfl_sync(FULLM, a0, q),
                                                     __shfl_sync(FULLM, a0, (q + 1) & 31), sh);
                const uint32_t r1w = __funnelshift_r(__shfl_sync(FULLM, a1, q),
                                                     __shfl_sync(FULLM, a1, (q + 1) & 31), sh);
                const uint32_t r2w = __funnelshift_r(__shfl_sync(FULLM, a2, q),
                                                     __shfl_sync(FULLM, a2, (q + 1) & 31), sh);
                float4 v;
                v.x = __uint_as_float((r0w & 1u) * ONEF)
                    + (__uint_as_float((r1w & 1u) * TWOF)
                     + __uint_as_float((r2w & 1u) * FOURF));
                v.y = __uint_as_float((r0w & 2u) * ONEF_2)
                    + (__uint_as_float((r1w & 2u) * TWOF_2)
                     + __uint_as_float((r2w & 2u) * FOURF_2));
                v.z = __uint_as_float((r0w & 4u) * ONEF_4)
                    + (__uint_as_float((r1w & 4u) * TWOF_4)
                     + __uint_as_float((r2w & 4u) * FOURF_4));
                v.w = __uint_as_float((r0w & 8u) * ONEF_8)
                    + (__uint_as_float((r1w & 8u) * TWOF_8)
                     + __uint_as_float((r2w & 8u) * FOURF_8));
                if (j < ng) __stcs(o4 + j, v);
            }
        }

        {   // ch4: turn broadcast
            const size_t gb = gb0 + 4 * CELLS;
            float* o = out + gb;
            const int s  = (int)((4u - ((uint32_t)gb & 3u)) & 3u);
            const int ng = (CELLS - s) >> 2;
            const int tb = s + 4 * ng;
            const int tc = CELLS - tb;
            float4* o4 = (float4*)(o + s);
            const float tv = (float)cp;
            if (lane < s)  __stcs(o + lane, tv);
            if (lane < tc) __stcs(o + tb + lane, tv);
            const float4 v = make_float4(tv, tv, tv, tv);
#pragma unroll
            for (int it = 0; it < 3; ++it) {
                const int j = it * 32 + lane;
                if (j < ng) __stcs(o4 + j, v);
            }
        }
    }
}

extern "C" void kernel_launch(void* const* d_in, const int* in_sizes, int n_in,
                              void* d_out, int out_size)
{
    const float* stones     = (const float*)d_in[0];
    const int*   cur_player = (const int*)  d_in[1];
    const int*   ko_points  = (const int*)  d_in[2];
    float*       out        = (float*)      d_out;

    const int B = in_sizes[1];

    int nsm = 148;
    cudaDeviceGetAttribute(&nsm, cudaDevAttrMultiProcessorCount, 0);
    int grid = nsm * 3;                        // exactly one resident wave
    const int maxg = (B + WPB - 1) / WPB;
    if (grid > maxg) grid = maxg;

    go_feat_kernel<<<grid, NT>>>(stones, cur_player, ko_points, out, B);
}

// round 16
// speedup vs baseline: 1.3103x; 1.3103x over previous
#include <cuda_runtime.h>
#include <cstdint>

#define HH 19
#define CELLS 361
#define MASK19 0x7FFFFu
#define NT 512
#define WPB 16                // warps (=boards) per block
#define FULLM 0xFFFFFFFFu

#define ONEF   0x3F800000u   // 1.0f
#define ONEF_2 0x1FC00000u   // *2 -> 1.0f
#define ONEF_4 0x0FE00000u   // *4 -> 1.0f
#define ONEF_8 0x07F00000u   // *8 -> 1.0f
#define TWOF   0x40000000u   // 2.0f
#define TWOF_2 0x20000000u
#define TWOF_4 0x10000000u
#define TWOF_8 0x08000000u
#define FOURF   0x40800000u  // 4.0f
#define FOURF_2 0x20400000u
#define FOURF_4 0x10200000u
#define FOURF_8 0x08100000u

// weak = opp stone with exactly one orthogonal opp neighbor
__device__ __forceinline__ uint32_t weak_row(uint32_t om, uint32_t ou, uint32_t od) {
    const uint32_t ol  = (om << 1) & MASK19;
    const uint32_t orr = om >> 1;
    const uint32_t par = ou ^ od ^ ol ^ orr;
    const uint32_t ge2 = (ou & od) | (ol & orr) | ((ou | od) & (ol | orr));
    return om & par & ~ge2;
}

// expand a 361-bit stream (word w in lane w, w=0..11) of 0/1 bits to floats
__device__ __forceinline__ void expand_binary(float* __restrict__ out,
                                              size_t gb, uint32_t S, int lane) {
    float* o = out + gb;
    const int s  = (int)((4u - ((uint32_t)gb & 3u)) & 3u);
    const int ng = (CELLS - s) >> 2;
    const int tb = s + 4 * ng;
    const int tc = CELLS - tb;
    float4* o4 = (float4*)(o + s);
    const uint32_t h = __shfl_sync(FULLM, S, 0);
    const uint32_t e = __shfl_sync(FULLM, S, 11);
    if (lane < s)  o[lane] = __uint_as_float(((h >> lane) & 1u) * ONEF);
    if (lane < tc) o[tb + lane] = __uint_as_float(((e >> (tb + lane - 352)) & 1u) * ONEF);
#pragma unroll
    for (int it = 0; it < 3; ++it) {
        const int j  = it * 32 + lane;
        const int bp = s + 4 * j;
        const int q  = bp >> 5, sh = bp & 31;
        const uint32_t pr = __funnelshift_r(__shfl_sync(FULLM, S, q),
                                            __shfl_sync(FULLM, S, (q + 1) & 31), sh);
        float4 v;
        v.x = __uint_as_float((pr & 1u) * ONEF);
        v.y = __uint_as_float((pr & 2u) * ONEF_2);
        v.z = __uint_as_float((pr & 4u) * ONEF_4);
        v.w = __uint_as_float((pr & 8u) * ONEF_8);
        if (j < ng) o4[j] = v;
    }
}

__global__ __launch_bounds__(NT, 2)
void go_feat_kernel(const float* __restrict__ stones,
                    const int*   __restrict__ cur_player,
                    const int*   __restrict__ ko_points,
                    float*       __restrict__ out,
                    int B)
{
    const int lane = threadIdx.x & 31;
    const int b    = blockIdx.x * WPB + (threadIdx.x >> 5);
    if (b >= B) return;                       // warp-uniform

    const int cp = cur_player[b];             // broadcast loads (same addr per warp)
    const int kr = ko_points[2 * b];
    const int kc = ko_points[2 * b + 1];

    // ---- 1: ballot-pack the board's 722 floats; word k parked in lane k ----
    // Two-pass: batch ALL loads first (MLP=23), then do the ballots.
    const float* src = stones + (size_t)b * 722;
    float vals[23];
#pragma unroll
    for (int k = 0; k < 23; ++k) {
        const int e = (k << 5) + lane;
        vals[k] = (e < 722) ? src[e] : 0.0f;
    }
    uint32_t W = 0u;
#pragma unroll
    for (int k = 0; k < 23; ++k) {
        const unsigned bal = __ballot_sync(FULLM, vals[k] > 0.5f);
        if (lane == k) W = bal;
    }

    // ---- 2: row masks; lane r = row r (lanes >= 19 forced to 0) ----
    const int bit0 = HH * lane;
    const uint32_t m0 = __funnelshift_r(__shfl_sync(FULLM, W, (bit0 >> 5) & 31),
                                        __shfl_sync(FULLM, W, ((bit0 >> 5) + 1) & 31),
                                        bit0) & MASK19;
    const int bit1 = bit0 + CELLS;
    const uint32_t m1 = __funnelshift_r(__shfl_sync(FULLM, W, (bit1 >> 5) & 31),
                                        __shfl_sync(FULLM, W, ((bit1 >> 5) + 1) & 31),
                                        bit1) & MASK19;
    const bool rowok = lane < HH;
    const uint32_t curb = rowok ? (cp ? m1 : m0) : 0u;
    const uint32_t oppb = rowok ? (cp ? m0 : m1) : 0u;
    const uint32_t empb = rowok ? ((~(m0 | m1)) & MASK19) : 0u;

    // ---- 3: stencils, lane-parallel (wrap-around shfl hits zeroed lanes) ----
    const uint32_t ou = __shfl_sync(FULLM, oppb, (lane - 1) & 31);
    const uint32_t od = __shfl_sync(FULLM, oppb, (lane + 1) & 31);
    const uint32_t wk  = weak_row(oppb, ou, od);
    const uint32_t wku = __shfl_sync(FULLM, wk, (lane - 1) & 31);
    const uint32_t wkd = __shfl_sync(FULLM, wk, (lane + 1) & 31);
    const uint32_t eu = __shfl_sync(FULLM, empb, (lane - 1) & 31);
    const uint32_t ed = __shfl_sync(FULLM, empb, (lane + 1) & 31);

    uint32_t legal = empb & (eu | ed | ((empb << 1) & MASK19) | (empb >> 1)
                   | wku | wkd | ((wk << 1) & MASK19) | (wk >> 1));
    if (kr >= 0) {
        const int rr = kr > (HH - 1) ? (HH - 1) : kr;
        int cc = kc < 0 ? 0 : (kc > (HH - 1) ? (HH - 1) : kc);
        if (lane == rr) legal &= ~(1u << cc);
    }

    const uint32_t cu = __shfl_sync(FULLM, curb, (lane - 1) & 31);
    const uint32_t cd = __shfl_sync(FULLM, curb, (lane + 1) & 31);
    const uint32_t cl = (curb << 1) & MASK19;
    const uint32_t cr = curb >> 1;
    const uint32_t sab = cu ^ cd,  cab = cu & cd;
    const uint32_t scd = cl ^ cr,  ccd = cl & cr;
    const uint32_t kx  = sab & scd;
    const uint32_t p0 = (sab ^ scd)      & empb;   // ones
    const uint32_t p1 = (cab ^ ccd ^ kx) & empb;   // twos
    const uint32_t p2 = (cab & ccd)      & empb;   // fours

    // ---- 4: build 361-bit streams (word w in lane w, w = 0..11) ----
    const int w32 = lane << 5;
    const int r0  = w32 / HH;
    uint32_t ls = 0u, a0 = 0u, a1 = 0u, a2 = 0u;
#pragma unroll
    for (int i = 0; i < 3; ++i) {
        const int r  = r0 + i;
        const int sh = HH * r - w32;               // (-19, 39)
        const uint32_t lm = __shfl_sync(FULLM, legal, r & 31);
        const uint32_t q0 = __shfl_sync(FULLM, p0,    r & 31);
        const uint32_t q1 = __shfl_sync(FULLM, p1,    r & 31);
        const uint32_t q2 = __shfl_sync(FULLM, p2,    r & 31);
        if (sh >= 0) {
            if (sh < 32) {
                ls |= lm << sh; a0 |= q0 << sh; a1 |= q1 << sh; a2 |= q2 << sh;
            }
        } else {
            ls |= lm >> (-sh); a0 |= q0 >> (-sh); a1 |= q1 >> (-sh); a2 |= q2 >> (-sh);
        }
    }
    // cur/opp streams come free from the packed input bits
    const int pbase = cp * CELLS + w32;
    const uint32_t cur_s = __funnelshift_r(__shfl_sync(FULLM, W, (pbase >> 5) & 31),
                                           __shfl_sync(FULLM, W, ((pbase >> 5) + 1) & 31),
                                           pbase);
    const int obase = (1 - cp) * CELLS + w32;
    const uint32_t opp_s = __funnelshift_r(__shfl_sync(FULLM, W, (obase >> 5) & 31),
                                           __shfl_sync(FULLM, W, ((obase >> 5) + 1) & 31),
                                           obase);

    // ---- 5: expansion, 5 channels ----
    const size_t gb0 = (size_t)b * 1805;
    expand_binary(out, gb0,             cur_s, lane);
    expand_binary(out, gb0 + CELLS,     opp_s, lane);
    expand_binary(out, gb0 + 2 * CELLS, ls,    lane);

    {   // ch3: liberties (0..7, exact)
        const size_t gb = gb0 + 3 * CELLS;
        float* o = out + gb;
        const int s  = (int)((4u - ((uint32_t)gb & 3u)) & 3u);
        const int ng = (CELLS - s) >> 2;
        const int tb = s + 4 * ng;
        const int tc = CELLS - tb;
        float4* o4 = (float4*)(o + s);
        const uint32_t h0 = __shfl_sync(FULLM, a0, 0);
        const uint32_t h1 = __shfl_sync(FULLM, a1, 0);
        const uint32_t h2 = __shfl_sync(FULLM, a2, 0);
        const uint32_t e0 = __shfl_sync(FULLM, a0, 11);
        const uint32_t e1 = __shfl_sync(FULLM, a1, 11);
        const uint32_t e2 = __shfl_sync(FULLM, a2, 11);
        if (lane < s) {
            o[lane] = __uint_as_float(((h0 >> lane) & 1u) * ONEF)
                    + __uint_as_float(((h1 >> lane) & 1u) * TWOF)
                    + __uint_as_float(((h2 >> lane) & 1u) * FOURF);
        }
        if (lane < tc) {
            const int sh = tb + lane - 352;
            o[tb + lane] = __uint_as_float(((e0 >> sh) & 1u) * ONEF)
                         + __uint_as_float(((e1 >> sh) & 1u) * TWOF)
                         + __uint_as_float(((e2 >> sh) & 1u) * FOURF);
        }
#pragma unroll
        for (int it = 0; it < 3; ++it) {
            const int j  = it * 32 + lane;
            const int bp = s + 4 * j;
            const int q  = bp >> 5, sh = bp & 31;
            const uint32_t r0w = __funnelshift_r(__shfl_sync(FULLM, a0, q),
                                                 __shfl_sync(FULLM, a0, (q + 1) & 31), sh);
            const uint32_t r1w = __funnelshift_r(__shfl_sync(FULLM, a1, q),
                                                 __shfl_sync(FULLM, a1, (q + 1) & 31), sh);
            const uint32_t r2w = __funnelshift_r(__shfl_sync(FULLM, a2, q),
                                                 __shfl_sync(FULLM, a2, (q + 1) & 31), sh);
            float4 v;
            v.x = __uint_as_float((r0w & 1u) * ONEF)
                + (__uint_as_float((r1w & 1u) * TWOF)
                 + __uint_as_float((r2w & 1u) * FOURF));
            v.y = __uint_as_float((r0w & 2u) * ONEF_2)
                + (__uint_as_float((r1w & 2u) * TWOF_2)
                 + __uint_as_float((r2w & 2u) * FOURF_2));
            v.z = __uint_as_float((r0w & 4u) * ONEF_4)
                + (__uint_as_float((r1w & 4u) * TWOF_4)
                 + __uint_as_float((r2w & 4u) * FOURF_4));
            v.w = __uint_as_float((r0w & 8u) * ONEF_8)
                + (__uint_as_float((r1w & 8u) * TWOF_8)
                 + __uint_as_float((r2w & 8u) * FOURF_8));
            if (j < ng) o4[j] = v;
        }
    }

    {   // ch4: turn broadcast
        const size_t gb = gb0 + 4 * CELLS;
        float* o = out + gb;
        const int s  = (int)((4u - ((uint32_t)gb & 3u)) & 3u);
        const int ng = (CELLS - s) >> 2;
        const int tb = s + 4 * ng;
        const int tc = CELLS - tb;
        float4* o4 = (float4*)(o + s);
        const float tv = (float)cp;
        if (lane < s)  o[lane] = tv;
        if (lane < tc) o[tb + lane] = tv;
        const float4 v = make_float4(tv, tv, tv, tv);
#pragma unroll
        for (int it = 0; it < 3; ++it) {
            const int j = it * 32 + lane;
            if (j < ng) o4[j] = v;
        }
    }
}

extern "C" void kernel_launch(void* const* d_in, const int* in_sizes, int n_in,
                              void* d_out, int out_size)
{
    const float* stones     = (const float*)d_in[0];
    const int*   cur_player = (const int*)  d_in[1];
    const int*   ko_points  = (const int*)  d_in[2];
    float*       out        = (float*)      d_out;

    const int B = in_sizes[1];
    const int grid = (B + WPB - 1) / WPB;
    go_feat_kernel<<<grid, NT>>>(stones, cur_player, ko_points, out, B);
}